// round 2
// baseline (speedup 1.0000x reference)
#include <cuda_runtime.h>
#include <math.h>

#define D_MODEL 1024
#define NHEAD   16
#define D_HEAD  64
#define B_      2
#define S_      2048
#define M_ROWS  (B_*S_)     // 4096
#define KT      32          // k-tile in attention

// Scratch (allocation-free): projected Q/K/V and attention output, flat (B,S,D_MODEL)
__device__ float g_q [M_ROWS * D_MODEL];
__device__ float g_k [M_ROWS * D_MODEL];
__device__ float g_v [M_ROWS * D_MODEL];
__device__ float g_ao[M_ROWS * D_MODEL];

// ---------------------------------------------------------------------------
// C[m,n] = sum_k A[m*K+k] * W[n*K+k]   (both K-contiguous; W plays B^T)
// 128x128 tile, BK=8, 256 threads, 8x8 per thread.
// ---------------------------------------------------------------------------
__global__ __launch_bounds__(256) void sgemm_nt(
    const float* __restrict__ A, const float* __restrict__ W,
    float* __restrict__ C, int M, int N, int K)
{
    __shared__ float As[8][132];
    __shared__ float Bs[8][132];

    const int tid   = threadIdx.x;
    const int m0    = blockIdx.y * 128;
    const int n0    = blockIdx.x * 128;
    const int ldRow = tid >> 1;           // 0..127
    const int ldCol = (tid & 1) << 2;     // 0 or 4
    const int tx    = tid & 15;
    const int ty    = tid >> 4;

    const float* Ap = A + (size_t)(m0 + ldRow) * K + ldCol;
    const float* Wp = W + (size_t)(n0 + ldRow) * K + ldCol;

    float acc[8][8];
    #pragma unroll
    for (int i = 0; i < 8; i++)
        #pragma unroll
        for (int j = 0; j < 8; j++) acc[i][j] = 0.f;

    for (int k0 = 0; k0 < K; k0 += 8) {
        float4 a4 = *(const float4*)(Ap + k0);
        float4 b4 = *(const float4*)(Wp + k0);
        __syncthreads();
        As[ldCol+0][ldRow] = a4.x; As[ldCol+1][ldRow] = a4.y;
        As[ldCol+2][ldRow] = a4.z; As[ldCol+3][ldRow] = a4.w;
        Bs[ldCol+0][ldRow] = b4.x; Bs[ldCol+1][ldRow] = b4.y;
        Bs[ldCol+2][ldRow] = b4.z; Bs[ldCol+3][ldRow] = b4.w;
        __syncthreads();
        #pragma unroll
        for (int kk = 0; kk < 8; kk++) {
            float4 ma = *(const float4*)&As[kk][ty * 8];
            float4 mb = *(const float4*)&As[kk][ty * 8 + 4];
            float4 na = *(const float4*)&Bs[kk][tx * 8];
            float4 nb = *(const float4*)&Bs[kk][tx * 8 + 4];
            float rm[8] = {ma.x, ma.y, ma.z, ma.w, mb.x, mb.y, mb.z, mb.w};
            float rn[8] = {na.x, na.y, na.z, na.w, nb.x, nb.y, nb.z, nb.w};
            #pragma unroll
            for (int i = 0; i < 8; i++)
                #pragma unroll
                for (int j = 0; j < 8; j++)
                    acc[i][j] = fmaf(rm[i], rn[j], acc[i][j]);
        }
    }

    #pragma unroll
    for (int i = 0; i < 8; i++) {
        float* crow = C + (size_t)(m0 + ty * 8 + i) * N + n0 + tx * 8;
        *(float4*)(crow)     = make_float4(acc[i][0], acc[i][1], acc[i][2], acc[i][3]);
        *(float4*)(crow + 4) = make_float4(acc[i][4], acc[i][5], acc[i][6], acc[i][7]);
    }
}

// ---------------------------------------------------------------------------
// Flash attention over the FLAT-reshaped heads.
// grid = (S/64, B*NHEAD); 256 threads = 8 warps; warp w owns q-rows w*8..w*8+7.
// Lane = tk within a 32-wide k-tile; lane also owns output dims (2*lane, 2*lane+1).
// ---------------------------------------------------------------------------
__device__ __forceinline__ float warpMax(float v) {
    #pragma unroll
    for (int o = 16; o > 0; o >>= 1) v = fmaxf(v, __shfl_xor_sync(0xffffffffu, v, o));
    return v;
}
__device__ __forceinline__ float warpSum(float v) {
    #pragma unroll
    for (int o = 16; o > 0; o >>= 1) v += __shfl_xor_sync(0xffffffffu, v, o);
    return v;
}

__global__ __launch_bounds__(256) void attn_kernel(const int* __restrict__ mask)
{
    __shared__ float Qs[64 * 64];        // 16 KB  (reads are broadcast)
    __shared__ float Ks[KT][68];         // padded: per-lane row reads conflict-free
    __shared__ float Vs[KT][68];
    __shared__ float Ps[8][KT][12];      // [warp][tk][row], row-stride 12 keeps f4 aligned

    const int tid   = threadIdx.x;
    const int w     = tid >> 5;
    const int lane  = tid & 31;
    const int bh    = blockIdx.y;        // b*16 + h
    const int b     = bh >> 4;
    const int qBase = blockIdx.x * 64;

    const size_t headOff = (size_t)bh * (S_ * D_HEAD);   // == b*S*D_MODEL + h*S*D_HEAD
    const float* Qg = g_q + headOff + (size_t)qBase * D_HEAD;
    const float* Kg = g_k + headOff;
    const float* Vg = g_v + headOff;
    const int* mrow =
        mask + (size_t)b * S_ * S_ + (size_t)qBase * S_ + (size_t)(w * 8) * S_;

    // Q tile is a contiguous 16KB slab (flat [t][d] layout)
    #pragma unroll
    for (int i = 0; i < 4; i++) {
        int off = tid * 4 + i * 1024;
        *(float4*)&Qs[off] = *(const float4*)&Qg[off];
    }

    float o0[8], o1[8], mrun[8], lrun[8];
    #pragma unroll
    for (int r = 0; r < 8; r++) { o0[r] = 0.f; o1[r] = 0.f; mrun[r] = -INFINITY; lrun[r] = 0.f; }

    for (int k0 = 0; k0 < S_; k0 += KT) {
        __syncthreads();
        {   // cooperative K/V tile load (contiguous 8KB each)
            int off = tid * 8;
            int row = off >> 6;
            int col = off & 63;
            const float* kp = Kg + (size_t)k0 * D_HEAD + off;
            const float* vp = Vg + (size_t)k0 * D_HEAD + off;
            *(float4*)&Ks[row][col]     = *(const float4*)(kp);
            *(float4*)&Ks[row][col + 4] = *(const float4*)(kp + 4);
            *(float4*)&Vs[row][col]     = *(const float4*)(vp);
            *(float4*)&Vs[row][col + 4] = *(const float4*)(vp + 4);
        }
        __syncthreads();

        // prefetch mask values (int32; nonzero = masked) — MLP=8
        int mb[8];
        #pragma unroll
        for (int r = 0; r < 8; r++)
            mb[r] = mrow[(size_t)r * S_ + k0 + lane];

        // scores: s[r] = Q[row r] . K[lane]
        float s[8];
        #pragma unroll
        for (int r = 0; r < 8; r++) s[r] = 0.f;
        #pragma unroll 4
        for (int j4 = 0; j4 < 16; j4++) {
            float4 k4 = *(const float4*)&Ks[lane][j4 * 4];
            #pragma unroll
            for (int r = 0; r < 8; r++) {
                float4 q4 = *(const float4*)&Qs[(w * 8 + r) * 64 + j4 * 4];
                s[r] = fmaf(q4.x, k4.x, s[r]);
                s[r] = fmaf(q4.y, k4.y, s[r]);
                s[r] = fmaf(q4.z, k4.z, s[r]);
                s[r] = fmaf(q4.w, k4.w, s[r]);
            }
        }

        // online softmax per row; stage p into smem for the PV pass
        #pragma unroll
        for (int r = 0; r < 8; r++) {
            float sv   = mb[r] ? -INFINITY : s[r] * 0.125f;   // 1/sqrt(64)
            float rmax = warpMax(sv);
            float nm   = fmaxf(mrun[r], rmax);
            float corr = __expf(mrun[r] - nm);
            if (nm == -INFINITY) corr = 1.0f;                 // all-masked-so-far guard
            float p = mb[r] ? 0.0f : __expf(sv - nm);
            mrun[r] = nm;
            lrun[r] = lrun[r] * corr + p;
            o0[r] *= corr; o1[r] *= corr;
            Ps[w][lane][r] = p;
        }
        __syncwarp();

        // PV: V tile read ONCE per tk (p broadcast from smem)
        #pragma unroll 8
        for (int tk = 0; tk < KT; tk++) {
            float4 pa = *(const float4*)&Ps[w][tk][0];
            float4 pb = *(const float4*)&Ps[w][tk][4];
            float2 v2 = *(const float2*)&Vs[tk][lane * 2];
            o0[0] = fmaf(pa.x, v2.x, o0[0]); o1[0] = fmaf(pa.x, v2.y, o1[0]);
            o0[1] = fmaf(pa.y, v2.x, o0[1]); o1[1] = fmaf(pa.y, v2.y, o1[1]);
            o0[2] = fmaf(pa.z, v2.x, o0[2]); o1[2] = fmaf(pa.z, v2.y, o1[2]);
            o0[3] = fmaf(pa.w, v2.x, o0[3]); o1[3] = fmaf(pa.w, v2.y, o1[3]);
            o0[4] = fmaf(pb.x, v2.x, o0[4]); o1[4] = fmaf(pb.x, v2.y, o1[4]);
            o0[5] = fmaf(pb.y, v2.x, o0[5]); o1[5] = fmaf(pb.y, v2.y, o1[5]);
            o0[6] = fmaf(pb.z, v2.x, o0[6]); o1[6] = fmaf(pb.z, v2.y, o1[6]);
            o0[7] = fmaf(pb.w, v2.x, o0[7]); o1[7] = fmaf(pb.w, v2.y, o1[7]);
        }
        __syncwarp();
    }

    #pragma unroll
    for (int r = 0; r < 8; r++) {
        float lsum = warpSum(lrun[r]);
        float inv  = 1.0f / lsum;
        float2 res = make_float2(o0[r] * inv, o1[r] * inv);
        *(float2*)&g_ao[headOff + (size_t)(qBase + w * 8 + r) * D_HEAD + lane * 2] = res;
    }
}

// ---------------------------------------------------------------------------
extern "C" void kernel_launch(void* const* d_in, const int* in_sizes, int n_in,
                              void* d_out, int out_size)
{
    const float* q  = (const float*)d_in[0];
    const float* k  = (const float*)d_in[1];
    const float* v  = (const float*)d_in[2];
    const int*   mask = (const int*)d_in[3];
    const float* w_q = (const float*)d_in[4];
    const float* w_k = (const float*)d_in[5];
    const float* w_v = (const float*)d_in[6];
    const float* w_o = (const float*)d_in[7];
    float* out = (float*)d_out;

    float *pq, *pk, *pv, *pa;
    cudaGetSymbolAddress((void**)&pq, g_q);
    cudaGetSymbolAddress((void**)&pk, g_k);
    cudaGetSymbolAddress((void**)&pv, g_v);
    cudaGetSymbolAddress((void**)&pa, g_ao);

    dim3 gb(D_MODEL / 128, M_ROWS / 128);   // (8, 32)
    sgemm_nt<<<gb, 256>>>(q, w_q, pq, M_ROWS, D_MODEL, D_MODEL);
    sgemm_nt<<<gb, 256>>>(k, w_k, pk, M_ROWS, D_MODEL, D_MODEL);
    sgemm_nt<<<gb, 256>>>(v, w_v, pv, M_ROWS, D_MODEL, D_MODEL);

    attn_kernel<<<dim3(S_ / 64, B_ * NHEAD), 256>>>(mask);

    sgemm_nt<<<gb, 256>>>(pa, w_o, out, M_ROWS, D_MODEL, D_MODEL);
}

// round 4
// speedup vs baseline: 1.3004x; 1.3004x over previous
#include <cuda_runtime.h>
#include <cuda_bf16.h>
#include <math.h>
#include <stdint.h>

#define D_MODEL 1024
#define NHEAD   16
#define D_HEAD  64
#define B_      2
#define S_      2048
#define M_ROWS  (B_*S_)     // 4096
#define KT      32          // k-tile in attention

// ---------------- scratch (allocation-free) ----------------
__device__ float g_q [M_ROWS * D_MODEL];
__device__ float g_k [M_ROWS * D_MODEL];
__device__ float g_v [M_ROWS * D_MODEL];
__device__ float g_ao[M_ROWS * D_MODEL];
__device__ __nv_bfloat16 g_ah[M_ROWS * D_MODEL];   // A hi
__device__ __nv_bfloat16 g_al[M_ROWS * D_MODEL];   // A lo
__device__ __nv_bfloat16 g_wh[D_MODEL * D_MODEL];  // W hi
__device__ __nv_bfloat16 g_wl[D_MODEL * D_MODEL];  // W lo

// ---------------- helpers ----------------
__device__ __forceinline__ uint32_t smem_u32(const void* p) {
    uint32_t a;
    asm("{ .reg .u64 t; cvta.to.shared.u64 t, %1; cvt.u32.u64 %0, t; }" : "=r"(a) : "l"(p));
    return a;
}
#define CP16(dst, src) \
    asm volatile("cp.async.cg.shared.global [%0], [%1], 16;" :: "r"(dst), "l"(src))
#define CP_COMMIT() asm volatile("cp.async.commit_group;" ::: "memory")
#define LDSM4(d, a) \
    asm volatile("ldmatrix.sync.aligned.m8n8.x4.shared.b16 {%0,%1,%2,%3}, [%4];" \
        : "=r"((d)[0]), "=r"((d)[1]), "=r"((d)[2]), "=r"((d)[3]) : "r"(a))
#define MMA16816(c, a, b0, b1) \
    asm volatile("mma.sync.aligned.m16n8k16.row.col.f32.bf16.bf16.f32 " \
        "{%0,%1,%2,%3},{%4,%5,%6,%7},{%8,%9},{%0,%1,%2,%3};" \
        : "+f"((c)[0]), "+f"((c)[1]), "+f"((c)[2]), "+f"((c)[3]) \
        : "r"((a)[0]), "r"((a)[1]), "r"((a)[2]), "r"((a)[3]), "r"(b0), "r"(b1))

// ---------------- fp32 -> (hi,lo) bf16 split ----------------
__global__ __launch_bounds__(256) void split_f32(
    const float* __restrict__ x, __nv_bfloat16* __restrict__ hi,
    __nv_bfloat16* __restrict__ lo, int n4)
{
    int i = blockIdx.x * blockDim.x + threadIdx.x;
    if (i >= n4) return;
    float4 v = ((const float4*)x)[i];
    __nv_bfloat162 h01 = __floats2bfloat162_rn(v.x, v.y);
    __nv_bfloat162 h23 = __floats2bfloat162_rn(v.z, v.w);
    float2 f01 = __bfloat1622float2(h01);
    float2 f23 = __bfloat1622float2(h23);
    __nv_bfloat162 l01 = __floats2bfloat162_rn(v.x - f01.x, v.y - f01.y);
    __nv_bfloat162 l23 = __floats2bfloat162_rn(v.z - f23.x, v.w - f23.y);
    uint2 hp, lp;
    hp.x = *reinterpret_cast<uint32_t*>(&h01); hp.y = *reinterpret_cast<uint32_t*>(&h23);
    lp.x = *reinterpret_cast<uint32_t*>(&l01); lp.y = *reinterpret_cast<uint32_t*>(&l23);
    ((uint2*)hi)[i] = hp;
    ((uint2*)lo)[i] = lp;
}

// ---------------- split-bf16 GEMM via mma.sync (HMMA.16816) ----------------
// C[m,n] = sum_k A[m,k]*W[n,k]; C = Ah*Wh + Ah*Wl + Al*Wh, fp32 accum.
// CTA 128x128, BK=32. 8 warps (4m x 2n), warp tile 32x64 (2 x m16, 8 x n8).
// smem: 4 tiles (Ah,Al,Wh,Wl) 128x32 bf16, padded row stride 40 bf16 (80B,
// conflict-free for ldmatrix), double-buffered. 2-stage cp.async pipeline.
#define GS_STRIDE 80                     // bytes per smem row
#define GS_TILE   (128 * GS_STRIDE)      // 10240 B
#define GS_STAGE  (4 * GS_TILE)          // 40960 B
#define GSMEM     (2 * GS_STAGE)         // 81920 B
#define NKB       (D_MODEL / 32)         // 32 K-chunks

__global__ __launch_bounds__(256) void gemm_tc(
    const __nv_bfloat16* __restrict__ Ah, const __nv_bfloat16* __restrict__ Al,
    const __nv_bfloat16* __restrict__ Wh, const __nv_bfloat16* __restrict__ Wl,
    float* __restrict__ C)
{
    extern __shared__ char sm[];
    const uint32_t sbase = smem_u32(sm);
    const int tid  = threadIdx.x;
    const int wid  = tid >> 5, lane = tid & 31;
    const int wm   = wid & 3,  wn   = wid >> 2;       // warp grid 4x2
    const int m0   = blockIdx.y * 128, n0 = blockIdx.x * 128;

    const __nv_bfloat16* srcs[4] = {Ah, Al, Wh, Wl};
    const int rb[4] = {m0, m0, n0, n0};

    // async-load one BK=32 chunk (all 4 tiles) into stage s
    auto load_stage = [&](int kb, int s) {
        const int k0 = kb * 32;
        const uint32_t stb = sbase + s * GS_STAGE;
        #pragma unroll
        for (int j = 0; j < 8; j++) {
            int c    = j * 256 + tid;            // 0..2047
            int tile = c >> 9;
            int r    = (c >> 2) & 127;
            int cc   = c & 3;
            uint32_t dst = stb + tile * GS_TILE + r * GS_STRIDE + cc * 16;
            const __nv_bfloat16* src = srcs[tile] + ((size_t)(rb[tile] + r) << 10) + k0 + cc * 8;
            CP16(dst, src);
        }
        CP_COMMIT();
    };

    float acc[2][8][4];
    #pragma unroll
    for (int mt = 0; mt < 2; mt++)
        #pragma unroll
        for (int nt = 0; nt < 8; nt++)
            #pragma unroll
            for (int e = 0; e < 4; e++) acc[mt][nt][e] = 0.f;

    // ldmatrix lane address components
    const int lr   = lane & 7;
    const int ls8  = ((lane >> 3) & 1) << 3;      // +8 rows for matrices 1,3
    const int lc16 = ((lane >> 4) & 1) << 4;      // +16B for matrices 2,3

    load_stage(0, 0);

    for (int kb = 0; kb < NKB; kb++) {
        if (kb + 1 < NKB) {
            load_stage(kb + 1, (kb + 1) & 1);
            asm volatile("cp.async.wait_group 1;" ::: "memory");
        } else {
            asm volatile("cp.async.wait_group 0;" ::: "memory");
        }
        __syncthreads();

        const uint32_t stb = sbase + (kb & 1) * GS_STAGE;
        #pragma unroll
        for (int k16 = 0; k16 < 2; k16++) {
            const uint32_t colOff = k16 * 32 + lc16;
            uint32_t ah[2][4], al[2][4], bh[4][4], bl[4][4];
            #pragma unroll
            for (int mt = 0; mt < 2; mt++) {
                uint32_t rowA = wm * 32 + mt * 16 + lr + ls8;
                LDSM4(ah[mt], stb + 0 * GS_TILE + rowA * GS_STRIDE + colOff);
                LDSM4(al[mt], stb + 1 * GS_TILE + rowA * GS_STRIDE + colOff);
            }
            #pragma unroll
            for (int np = 0; np < 4; np++) {
                uint32_t rowB = wn * 64 + np * 16 + lr + ls8;
                LDSM4(bh[np], stb + 2 * GS_TILE + rowB * GS_STRIDE + colOff);
                LDSM4(bl[np], stb + 3 * GS_TILE + rowB * GS_STRIDE + colOff);
            }
            #pragma unroll
            for (int mt = 0; mt < 2; mt++)
                #pragma unroll
                for (int nt = 0; nt < 8; nt++) {
                    const int np = nt >> 1, s = nt & 1;
                    MMA16816(acc[mt][nt], ah[mt], bh[np][s], bh[np][s + 2]);
                    MMA16816(acc[mt][nt], ah[mt], bl[np][s], bl[np][s + 2]);
                    MMA16816(acc[mt][nt], al[mt], bh[np][s], bh[np][s + 2]);
                }
        }
        __syncthreads();
    }

    // epilogue: c0,c1 -> (row, col..col+1); c2,c3 -> (row+8, ...)
    const int erow = lane >> 2, ecol = (lane & 3) << 1;
    #pragma unroll
    for (int mt = 0; mt < 2; mt++)
        #pragma unroll
        for (int nt = 0; nt < 8; nt++) {
            int gr = m0 + wm * 32 + mt * 16 + erow;
            int gc = n0 + wn * 64 + nt * 8 + ecol;
            *(float2*)&C[(size_t)gr * D_MODEL + gc] =
                make_float2(acc[mt][nt][0], acc[mt][nt][1]);
            *(float2*)&C[(size_t)(gr + 8) * D_MODEL + gc] =
                make_float2(acc[mt][nt][2], acc[mt][nt][3]);
        }
}

// ---------------- SIMT flash attention (unchanged) ----------------
__device__ __forceinline__ float warpMax(float v) {
    #pragma unroll
    for (int o = 16; o > 0; o >>= 1) v = fmaxf(v, __shfl_xor_sync(0xffffffffu, v, o));
    return v;
}
__device__ __forceinline__ float warpSum(float v) {
    #pragma unroll
    for (int o = 16; o > 0; o >>= 1) v += __shfl_xor_sync(0xffffffffu, v, o);
    return v;
}

__global__ __launch_bounds__(256) void attn_kernel(const int* __restrict__ mask)
{
    __shared__ float Qs[64 * 64];
    __shared__ float Ks[KT][68];
    __shared__ float Vs[KT][68];
    __shared__ float Ps[8][KT][12];

    const int tid   = threadIdx.x;
    const int w     = tid >> 5;
    const int lane  = tid & 31;
    const int bh    = blockIdx.y;
    const int b     = bh >> 4;
    const int qBase = blockIdx.x * 64;

    const size_t headOff = (size_t)bh * (S_ * D_HEAD);
    const float* Qg = g_q + headOff + (size_t)qBase * D_HEAD;
    const float* Kg = g_k + headOff;
    const float* Vg = g_v + headOff;
    const int* mrow = mask + (size_t)b * S_ * S_ + (size_t)qBase * S_ + (size_t)(w * 8) * S_;

    #pragma unroll
    for (int i = 0; i < 4; i++) {
        int off = tid * 4 + i * 1024;
        *(float4*)&Qs[off] = *(const float4*)&Qg[off];
    }

    float o0[8], o1[8], mrun[8], lrun[8];
    #pragma unroll
    for (int r = 0; r < 8; r++) { o0[r] = 0.f; o1[r] = 0.f; mrun[r] = -INFINITY; lrun[r] = 0.f; }

    for (int k0 = 0; k0 < S_; k0 += KT) {
        __syncthreads();
        {
            int off = tid * 8;
            int row = off >> 6;
            int col = off & 63;
            const float* kp = Kg + (size_t)k0 * D_HEAD + off;
            const float* vp = Vg + (size_t)k0 * D_HEAD + off;
            *(float4*)&Ks[row][col]     = *(const float4*)(kp);
            *(float4*)&Ks[row][col + 4] = *(const float4*)(kp + 4);
            *(float4*)&Vs[row][col]     = *(const float4*)(vp);
            *(float4*)&Vs[row][col + 4] = *(const float4*)(vp + 4);
        }
        __syncthreads();

        int mb[8];
        #pragma unroll
        for (int r = 0; r < 8; r++)
            mb[r] = mrow[(size_t)r * S_ + k0 + lane];

        float s[8];
        #pragma unroll
        for (int r = 0; r < 8; r++) s[r] = 0.f;
        #pragma unroll 4
        for (int j4 = 0; j4 < 16; j4++) {
            float4 k4 = *(const float4*)&Ks[lane][j4 * 4];
            #pragma unroll
            for (int r = 0; r < 8; r++) {
                float4 q4 = *(const float4*)&Qs[(w * 8 + r) * 64 + j4 * 4];
                s[r] = fmaf(q4.x, k4.x, s[r]);
                s[r] = fmaf(q4.y, k4.y, s[r]);
                s[r] = fmaf(q4.z, k4.z, s[r]);
                s[r] = fmaf(q4.w, k4.w, s[r]);
            }
        }

        #pragma unroll
        for (int r = 0; r < 8; r++) {
            float sv   = mb[r] ? -INFINITY : s[r] * 0.125f;
            float rmax = warpMax(sv);
            float nm   = fmaxf(mrun[r], rmax);
            float corr = __expf(mrun[r] - nm);
            if (nm == -INFINITY) corr = 1.0f;
            float p = mb[r] ? 0.0f : __expf(sv - nm);
            mrun[r] = nm;
            lrun[r] = lrun[r] * corr + p;
            o0[r] *= corr; o1[r] *= corr;
            Ps[w][lane][r] = p;
        }
        __syncwarp();

        #pragma unroll 8
        for (int tk = 0; tk < KT; tk++) {
            float4 pa = *(const float4*)&Ps[w][tk][0];
            float4 pb = *(const float4*)&Ps[w][tk][4];
            float2 v2 = *(const float2*)&Vs[tk][lane * 2];
            o0[0] = fmaf(pa.x, v2.x, o0[0]); o1[0] = fmaf(pa.x, v2.y, o1[0]);
            o0[1] = fmaf(pa.y, v2.x, o0[1]); o1[1] = fmaf(pa.y, v2.y, o1[1]);
            o0[2] = fmaf(pa.z, v2.x, o0[2]); o1[2] = fmaf(pa.z, v2.y, o1[2]);
            o0[3] = fmaf(pa.w, v2.x, o0[3]); o1[3] = fmaf(pa.w, v2.y, o1[3]);
            o0[4] = fmaf(pb.x, v2.x, o0[4]); o1[4] = fmaf(pb.x, v2.y, o1[4]);
            o0[5] = fmaf(pb.y, v2.x, o0[5]); o1[5] = fmaf(pb.y, v2.y, o1[5]);
            o0[6] = fmaf(pb.z, v2.x, o0[6]); o1[6] = fmaf(pb.z, v2.y, o1[6]);
            o0[7] = fmaf(pb.w, v2.x, o0[7]); o1[7] = fmaf(pb.w, v2.y, o1[7]);
        }
        __syncwarp();
    }

    #pragma unroll
    for (int r = 0; r < 8; r++) {
        float lsum = warpSum(lrun[r]);
        float inv  = 1.0f / lsum;
        float2 res = make_float2(o0[r] * inv, o1[r] * inv);
        *(float2*)&g_ao[headOff + (size_t)(qBase + w * 8 + r) * D_HEAD + lane * 2] = res;
    }
}

// ---------------------------------------------------------------------------
extern "C" void kernel_launch(void* const* d_in, const int* in_sizes, int n_in,
                              void* d_out, int out_size)
{
    const float* q    = (const float*)d_in[0];
    const float* k    = (const float*)d_in[1];
    const float* v    = (const float*)d_in[2];
    const int*   mask = (const int*)d_in[3];
    const float* w_q  = (const float*)d_in[4];
    const float* w_k  = (const float*)d_in[5];
    const float* w_v  = (const float*)d_in[6];
    const float* w_o  = (const float*)d_in[7];
    float* out = (float*)d_out;

    float *pq, *pk, *pv, *pa;
    __nv_bfloat16 *pah, *pal, *pwh, *pwl;
    cudaGetSymbolAddress((void**)&pq,  g_q);
    cudaGetSymbolAddress((void**)&pk,  g_k);
    cudaGetSymbolAddress((void**)&pv,  g_v);
    cudaGetSymbolAddress((void**)&pa,  g_ao);
    cudaGetSymbolAddress((void**)&pah, g_ah);
    cudaGetSymbolAddress((void**)&pal, g_al);
    cudaGetSymbolAddress((void**)&pwh, g_wh);
    cudaGetSymbolAddress((void**)&pwl, g_wl);

    cudaFuncSetAttribute(gemm_tc, cudaFuncAttributeMaxDynamicSharedMemorySize, GSMEM);

    const int nA4 = M_ROWS * D_MODEL / 4;
    const int nW4 = D_MODEL * D_MODEL / 4;
    dim3 gg(D_MODEL / 128, M_ROWS / 128);     // (8, 32)

    split_f32<<<nA4 / 256, 256>>>(q,   pah, pal, nA4);
    split_f32<<<nW4 / 256, 256>>>(w_q, pwh, pwl, nW4);
    gemm_tc<<<gg, 256, GSMEM>>>(pah, pal, pwh, pwl, pq);

    split_f32<<<nA4 / 256, 256>>>(k,   pah, pal, nA4);
    split_f32<<<nW4 / 256, 256>>>(w_k, pwh, pwl, nW4);
    gemm_tc<<<gg, 256, GSMEM>>>(pah, pal, pwh, pwl, pk);

    split_f32<<<nA4 / 256, 256>>>(v,   pah, pal, nA4);
    split_f32<<<nW4 / 256, 256>>>(w_v, pwh, pwl, nW4);
    gemm_tc<<<gg, 256, GSMEM>>>(pah, pal, pwh, pwl, pv);

    attn_kernel<<<dim3(S_ / 64, B_ * NHEAD), 256>>>(mask);

    split_f32<<<nA4 / 256, 256>>>(pa,  pah, pal, nA4);
    split_f32<<<nW4 / 256, 256>>>(w_o, pwh, pwl, nW4);
    gemm_tc<<<gg, 256, GSMEM>>>(pah, pal, pwh, pwl, out);
}

// round 5
// speedup vs baseline: 2.6064x; 2.0043x over previous
#include <cuda_runtime.h>
#include <cuda_bf16.h>
#include <math.h>
#include <stdint.h>

#define D_MODEL 1024
#define NHEAD   16
#define D_HEAD  64
#define B_      2
#define S_      2048
#define M_ROWS  (B_*S_)     // 4096

// ---------------- scratch (allocation-free) ----------------
__device__ float g_q [M_ROWS * D_MODEL];
__device__ float g_k [M_ROWS * D_MODEL];
__device__ float g_v [M_ROWS * D_MODEL];
__device__ float g_ao[M_ROWS * D_MODEL];
__device__ __nv_bfloat16 g_ah[M_ROWS * D_MODEL];   // GEMM A hi
__device__ __nv_bfloat16 g_al[M_ROWS * D_MODEL];   // GEMM A lo
__device__ __nv_bfloat16 g_wh[D_MODEL * D_MODEL];  // GEMM W hi
__device__ __nv_bfloat16 g_wl[D_MODEL * D_MODEL];  // GEMM W lo
// attention operands
__device__ __nv_bfloat16 g_qh[M_ROWS * D_MODEL];   // scaled Q hi/lo
__device__ __nv_bfloat16 g_ql[M_ROWS * D_MODEL];
__device__ __nv_bfloat16 g_kh[M_ROWS * D_MODEL];
__device__ __nv_bfloat16 g_kl[M_ROWS * D_MODEL];
__device__ __nv_bfloat16 g_vth[M_ROWS * D_MODEL];  // V^T per head [bh][64][2048]
__device__ __nv_bfloat16 g_vtl[M_ROWS * D_MODEL];
__device__ uint32_t      g_mbits[B_ * S_ * (S_/32)];  // packed mask bits

// ---------------- helpers ----------------
__device__ __forceinline__ uint32_t smem_u32(const void* p) {
    uint32_t a;
    asm("{ .reg .u64 t; cvta.to.shared.u64 t, %1; cvt.u32.u64 %0, t; }" : "=r"(a) : "l"(p));
    return a;
}
#define CP16(dst, src) \
    asm volatile("cp.async.cg.shared.global [%0], [%1], 16;" :: "r"(dst), "l"(src))
#define CP_COMMIT() asm volatile("cp.async.commit_group;" ::: "memory")
#define LDSM4(d, a) \
    asm volatile("ldmatrix.sync.aligned.m8n8.x4.shared.b16 {%0,%1,%2,%3}, [%4];" \
        : "=r"((d)[0]), "=r"((d)[1]), "=r"((d)[2]), "=r"((d)[3]) : "r"(a))
#define MMA16816(c, a, b0, b1) \
    asm volatile("mma.sync.aligned.m16n8k16.row.col.f32.bf16.bf16.f32 " \
        "{%0,%1,%2,%3},{%4,%5,%6,%7},{%8,%9},{%0,%1,%2,%3};" \
        : "+f"((c)[0]), "+f"((c)[1]), "+f"((c)[2]), "+f"((c)[3]) \
        : "r"((a)[0]), "r"((a)[1]), "r"((a)[2]), "r"((a)[3]), "r"(b0), "r"(b1))

// ---------------- fp32 -> (hi,lo) bf16 split, optional scale ----------------
__global__ __launch_bounds__(256) void split_f32(
    const float* __restrict__ x, __nv_bfloat16* __restrict__ hi,
    __nv_bfloat16* __restrict__ lo, int n4, float scale)
{
    int i = blockIdx.x * blockDim.x + threadIdx.x;
    if (i >= n4) return;
    float4 v = ((const float4*)x)[i];
    v.x *= scale; v.y *= scale; v.z *= scale; v.w *= scale;
    __nv_bfloat162 h01 = __floats2bfloat162_rn(v.x, v.y);
    __nv_bfloat162 h23 = __floats2bfloat162_rn(v.z, v.w);
    float2 f01 = __bfloat1622float2(h01);
    float2 f23 = __bfloat1622float2(h23);
    __nv_bfloat162 l01 = __floats2bfloat162_rn(v.x - f01.x, v.y - f01.y);
    __nv_bfloat162 l23 = __floats2bfloat162_rn(v.z - f23.x, v.w - f23.y);
    uint2 hp, lp;
    hp.x = *reinterpret_cast<uint32_t*>(&h01); hp.y = *reinterpret_cast<uint32_t*>(&h23);
    lp.x = *reinterpret_cast<uint32_t*>(&l01); lp.y = *reinterpret_cast<uint32_t*>(&l23);
    ((uint2*)hi)[i] = hp;
    ((uint2*)lo)[i] = lp;
}

// ---------------- V transpose + split:  [bh][key][d] -> [bh][d][key] ----------------
__global__ __launch_bounds__(256) void vtrans_split(void)
{
    __shared__ float t[32][33];
    const int bh = blockIdx.z, kt = blockIdx.x, dt = blockIdx.y;
    const int tx = threadIdx.x, ty = threadIdx.y;
    const size_t ho = (size_t)bh * S_ * D_HEAD;
    #pragma unroll
    for (int i = 0; i < 4; i++) {
        int key = kt * 32 + ty + i * 8;
        t[ty + i * 8][tx] = g_v[ho + (size_t)key * D_HEAD + dt * 32 + tx];
    }
    __syncthreads();
    #pragma unroll
    for (int i = 0; i < 4; i++) {
        int d   = dt * 32 + ty + i * 8;
        int key = kt * 32 + tx;
        float f = t[tx][ty + i * 8];
        __nv_bfloat16 h = __float2bfloat16_rn(f);
        g_vth[ho + (size_t)d * S_ + key] = h;
        g_vtl[ho + (size_t)d * S_ + key] = __float2bfloat16_rn(f - __bfloat162float(h));
    }
}

// ---------------- mask int32 -> bitmask ----------------
__global__ __launch_bounds__(256) void maskpack(const int* __restrict__ mask)
{
    int g = blockIdx.x * blockDim.x + threadIdx.x;
    int wid = g >> 5, lane = g & 31;
    // wid in [0, B*S*64): w = wid&63, q = (wid>>6)&2047, b = wid>>17
    int m = mask[((size_t)(wid >> 6) << 11) + ((wid & 63) << 5) + lane];
    uint32_t word = __ballot_sync(0xffffffffu, m != 0);
    if (lane == 0) g_mbits[wid] = word;
}

// ---------------- split-bf16 GEMM via mma.sync (unchanged from R4) ----------------
#define GS_STRIDE 80
#define GS_TILE   (128 * GS_STRIDE)
#define GS_STAGE  (4 * GS_TILE)
#define GSMEM     (2 * GS_STAGE)
#define NKB       (D_MODEL / 32)

__global__ __launch_bounds__(256) void gemm_tc(
    const __nv_bfloat16* __restrict__ Ah, const __nv_bfloat16* __restrict__ Al,
    const __nv_bfloat16* __restrict__ Wh, const __nv_bfloat16* __restrict__ Wl,
    float* __restrict__ C)
{
    extern __shared__ char sm[];
    const uint32_t sbase = smem_u32(sm);
    const int tid  = threadIdx.x;
    const int wid  = tid >> 5, lane = tid & 31;
    const int wm   = wid & 3,  wn   = wid >> 2;
    const int m0   = blockIdx.y * 128, n0 = blockIdx.x * 128;

    const __nv_bfloat16* srcs[4] = {Ah, Al, Wh, Wl};
    const int rb[4] = {m0, m0, n0, n0};

    auto load_stage = [&](int kb, int s) {
        const int k0 = kb * 32;
        const uint32_t stb = sbase + s * GS_STAGE;
        #pragma unroll
        for (int j = 0; j < 8; j++) {
            int c    = j * 256 + tid;
            int tile = c >> 9;
            int r    = (c >> 2) & 127;
            int cc   = c & 3;
            uint32_t dst = stb + tile * GS_TILE + r * GS_STRIDE + cc * 16;
            const __nv_bfloat16* src = srcs[tile] + ((size_t)(rb[tile] + r) << 10) + k0 + cc * 8;
            CP16(dst, src);
        }
        CP_COMMIT();
    };

    float acc[2][8][4];
    #pragma unroll
    for (int mt = 0; mt < 2; mt++)
        #pragma unroll
        for (int nt = 0; nt < 8; nt++)
            #pragma unroll
            for (int e = 0; e < 4; e++) acc[mt][nt][e] = 0.f;

    const int lr   = lane & 7;
    const int ls8  = ((lane >> 3) & 1) << 3;
    const int lc16 = ((lane >> 4) & 1) << 4;

    load_stage(0, 0);

    for (int kb = 0; kb < NKB; kb++) {
        if (kb + 1 < NKB) {
            load_stage(kb + 1, (kb + 1) & 1);
            asm volatile("cp.async.wait_group 1;" ::: "memory");
        } else {
            asm volatile("cp.async.wait_group 0;" ::: "memory");
        }
        __syncthreads();

        const uint32_t stb = sbase + (kb & 1) * GS_STAGE;
        #pragma unroll
        for (int k16 = 0; k16 < 2; k16++) {
            const uint32_t colOff = k16 * 32 + lc16;
            uint32_t ah[2][4], al[2][4], bh[4][4], bl[4][4];
            #pragma unroll
            for (int mt = 0; mt < 2; mt++) {
                uint32_t rowA = wm * 32 + mt * 16 + lr + ls8;
                LDSM4(ah[mt], stb + 0 * GS_TILE + rowA * GS_STRIDE + colOff);
                LDSM4(al[mt], stb + 1 * GS_TILE + rowA * GS_STRIDE + colOff);
            }
            #pragma unroll
            for (int np = 0; np < 4; np++) {
                uint32_t rowB = wn * 64 + np * 16 + lr + ls8;
                LDSM4(bh[np], stb + 2 * GS_TILE + rowB * GS_STRIDE + colOff);
                LDSM4(bl[np], stb + 3 * GS_TILE + rowB * GS_STRIDE + colOff);
            }
            #pragma unroll
            for (int mt = 0; mt < 2; mt++)
                #pragma unroll
                for (int nt = 0; nt < 8; nt++) {
                    const int np = nt >> 1, s = nt & 1;
                    MMA16816(acc[mt][nt], ah[mt], bh[np][s], bh[np][s + 2]);
                    MMA16816(acc[mt][nt], ah[mt], bl[np][s], bl[np][s + 2]);
                    MMA16816(acc[mt][nt], al[mt], bh[np][s], bh[np][s + 2]);
                }
        }
        __syncthreads();
    }

    const int erow = lane >> 2, ecol = (lane & 3) << 1;
    #pragma unroll
    for (int mt = 0; mt < 2; mt++)
        #pragma unroll
        for (int nt = 0; nt < 8; nt++) {
            int gr = m0 + wm * 32 + mt * 16 + erow;
            int gc = n0 + wn * 64 + nt * 8 + ecol;
            *(float2*)&C[(size_t)gr * D_MODEL + gc] =
                make_float2(acc[mt][nt][0], acc[mt][nt][1]);
            *(float2*)&C[(size_t)(gr + 8) * D_MODEL + gc] =
                make_float2(acc[mt][nt][2], acc[mt][nt][3]);
        }
}

// ---------------- tensor-core flash attention ----------------
// grid (S/128, B*NHEAD), 256 threads = 8 warps, warp w -> q rows w*16..w*16+15.
// K-tile 64. Scores: 3-pass split MMA; online softmax in C layout; PV: 3-pass.
#define AT_STRIDE 144                    // bytes per 64-bf16 smem row (conflict-free LDSM)
#define AT_QH 0
#define AT_QL 18432
#define AT_S0 36864
#define AT_KH 0
#define AT_KL 9216
#define AT_VH 18432
#define AT_VL 27648
#define AT_STAGE 36864
#define AT_SMEM (AT_S0 + 2 * AT_STAGE)   // 110592
#define AT_NT (S_ / 64)                  // 32 k-tiles

__global__ __launch_bounds__(256) void attn_tc(void)
{
    extern __shared__ char sm[];
    const uint32_t sbase = smem_u32(sm);
    const int tid = threadIdx.x, wid = tid >> 5, lane = tid & 31;
    const int bh  = blockIdx.y, b = bh >> 4;
    const int qBase = blockIdx.x * 128;
    const size_t ho = (size_t)bh * S_ * D_HEAD;

    const int lr   = lane & 7;
    const int ls8  = ((lane >> 3) & 1) << 3;
    const int lc16 = ((lane >> 4) & 1) << 4;
    const int r0   = lane >> 2, c2 = (lane & 3) << 1;

    // ---- load Q (both splits) into smem ----
    #pragma unroll
    for (int j = 0; j < 8; j++) {
        int c = j * 256 + tid;               // 0..2047
        int t = c >> 10, r = (c >> 3) & 127, cc = c & 7;
        uint32_t dst = sbase + (t ? AT_QL : AT_QH) + r * AT_STRIDE + cc * 16;
        const __nv_bfloat16* src = (t ? g_ql : g_qh) + ho + (size_t)(qBase + r) * D_HEAD + cc * 8;
        CP16(dst, src);
    }
    CP_COMMIT();

    // ---- stage loader: K/V tiles for k-tile kt -> stage s ----
    auto load_stage = [&](int kt, int s) {
        const int k0 = kt * 64;
        const uint32_t stb = sbase + AT_S0 + s * AT_STAGE;
        #pragma unroll
        for (int j = 0; j < 8; j++) {
            int c = j * 256 + tid;           // 0..2047
            int t = c >> 9, r = (c >> 3) & 63, cc = c & 7;
            uint32_t dst = stb + t * 9216 + r * AT_STRIDE + cc * 16;
            const __nv_bfloat16* src;
            if      (t == 0) src = g_kh  + ho + (size_t)(k0 + r) * D_HEAD + cc * 8;
            else if (t == 1) src = g_kl  + ho + (size_t)(k0 + r) * D_HEAD + cc * 8;
            else if (t == 2) src = g_vth + ho + (size_t)r * S_ + k0 + cc * 8;
            else             src = g_vtl + ho + (size_t)r * S_ + k0 + cc * 8;
            CP16(dst, src);
        }
        CP_COMMIT();
    };

    load_stage(0, 0);
    asm volatile("cp.async.wait_group 0;" ::: "memory");
    __syncthreads();

    // ---- preload Q fragments (4 k16 chunks, hi+lo) ----
    uint32_t qhf[4][4], qlf[4][4];
    {
        uint32_t rowA = wid * 16 + lr + ls8;
        #pragma unroll
        for (int kk = 0; kk < 4; kk++) {
            LDSM4(qhf[kk], sbase + AT_QH + rowA * AT_STRIDE + kk * 32 + lc16);
            LDSM4(qlf[kk], sbase + AT_QL + rowA * AT_STRIDE + kk * 32 + lc16);
        }
    }

    float O[8][4];
    #pragma unroll
    for (int nt = 0; nt < 8; nt++)
        #pragma unroll
        for (int e = 0; e < 4; e++) O[nt][e] = 0.f;
    float mr0 = -INFINITY, mr1 = -INFINITY, lr0s = 0.f, lr1s = 0.f;

    const int qg0 = qBase + wid * 16 + r0;   // global q row (row0)
    const size_t mrow0 = ((size_t)b * S_ + qg0) * (S_ / 32);
    const size_t mrow1 = mrow0 + 8 * (S_ / 32);

    for (int kt = 0; kt < AT_NT; kt++) {
        if (kt + 1 < AT_NT) {
            load_stage(kt + 1, (kt + 1) & 1);
            asm volatile("cp.async.wait_group 1;" ::: "memory");
        } else {
            asm volatile("cp.async.wait_group 0;" ::: "memory");
        }
        __syncthreads();

        const uint32_t stb = sbase + AT_S0 + (kt & 1) * AT_STAGE;

        // ---- scores: 3-pass split MMA ----
        float sc[8][4];
        #pragma unroll
        for (int nt = 0; nt < 8; nt++)
            #pragma unroll
            for (int e = 0; e < 4; e++) sc[nt][e] = 0.f;

        #pragma unroll
        for (int kk = 0; kk < 4; kk++) {
            #pragma unroll
            for (int np = 0; np < 4; np++) {
                uint32_t kbh[4], kbl[4];
                uint32_t rowB = (np * 16 + lr + ls8) * AT_STRIDE + kk * 32 + lc16;
                LDSM4(kbh, stb + AT_KH + rowB);
                LDSM4(kbl, stb + AT_KL + rowB);
                #pragma unroll
                for (int s = 0; s < 2; s++) {
                    const int nt = np * 2 + s;
                    MMA16816(sc[nt], qhf[kk], kbh[s], kbh[s + 2]);
                    MMA16816(sc[nt], qhf[kk], kbl[s], kbl[s + 2]);
                    MMA16816(sc[nt], qlf[kk], kbh[s], kbh[s + 2]);
                }
            }
        }

        // ---- mask ----
        uint32_t mw00 = g_mbits[mrow0 + kt * 2], mw01 = g_mbits[mrow0 + kt * 2 + 1];
        uint32_t mw10 = g_mbits[mrow1 + kt * 2], mw11 = g_mbits[mrow1 + kt * 2 + 1];
        #pragma unroll
        for (int nt = 0; nt < 8; nt++) {
            #pragma unroll
            for (int e = 0; e < 4; e++) {
                int key = nt * 8 + c2 + (e & 1);
                uint32_t word = (e < 2) ? ((key < 32) ? mw00 : mw01)
                                        : ((key < 32) ? mw10 : mw11);
                if ((word >> (key & 31)) & 1u) sc[nt][e] = -INFINITY;
            }
        }

        // ---- online softmax ----
        float tm0 = -INFINITY, tm1 = -INFINITY;
        #pragma unroll
        for (int nt = 0; nt < 8; nt++) {
            tm0 = fmaxf(tm0, fmaxf(sc[nt][0], sc[nt][1]));
            tm1 = fmaxf(tm1, fmaxf(sc[nt][2], sc[nt][3]));
        }
        tm0 = fmaxf(tm0, __shfl_xor_sync(0xffffffffu, tm0, 1));
        tm0 = fmaxf(tm0, __shfl_xor_sync(0xffffffffu, tm0, 2));
        tm1 = fmaxf(tm1, __shfl_xor_sync(0xffffffffu, tm1, 1));
        tm1 = fmaxf(tm1, __shfl_xor_sync(0xffffffffu, tm1, 2));

        float nm0 = fmaxf(mr0, tm0), nm1 = fmaxf(mr1, tm1);
        float corr0 = (mr0 == -INFINITY) ? 1.f : __expf(mr0 - nm0);
        float corr1 = (mr1 == -INFINITY) ? 1.f : __expf(mr1 - nm1);
        float b0 = (nm0 == -INFINITY) ? 0.f : nm0;
        float b1 = (nm1 == -INFINITY) ? 0.f : nm1;

        float ps0 = 0.f, ps1 = 0.f;
        #pragma unroll
        for (int nt = 0; nt < 8; nt++) {
            float p0 = __expf(sc[nt][0] - b0), p1 = __expf(sc[nt][1] - b0);
            float p2 = __expf(sc[nt][2] - b1), p3 = __expf(sc[nt][3] - b1);
            sc[nt][0] = p0; sc[nt][1] = p1; sc[nt][2] = p2; sc[nt][3] = p3;
            ps0 += p0 + p1; ps1 += p2 + p3;
        }
        lr0s = lr0s * corr0 + ps0;
        lr1s = lr1s * corr1 + ps1;
        mr0 = nm0; mr1 = nm1;
        #pragma unroll
        for (int nt = 0; nt < 8; nt++) {
            O[nt][0] *= corr0; O[nt][1] *= corr0;
            O[nt][2] *= corr1; O[nt][3] *= corr1;
        }

        // ---- PV: 3-pass split MMA, P repacked in-register ----
        #pragma unroll
        for (int kk2 = 0; kk2 < 4; kk2++) {
            uint32_t pah[4], pal[4];
            {
                const int ta = 2 * kk2, tb2 = 2 * kk2 + 1;
                __nv_bfloat162 h, l; float2 f;
                h = __floats2bfloat162_rn(sc[ta][0], sc[ta][1]);  f = __bfloat1622float2(h);
                l = __floats2bfloat162_rn(sc[ta][0] - f.x, sc[ta][1] - f.y);
                pah[0] = *(uint32_t*)&h; pal[0] = *(uint32_t*)&l;
                h = __floats2bfloat162_rn(sc[ta][2], sc[ta][3]);  f = __bfloat1622float2(h);
                l = __floats2bfloat162_rn(sc[ta][2] - f.x, sc[ta][3] - f.y);
                pah[1] = *(uint32_t*)&h; pal[1] = *(uint32_t*)&l;
                h = __floats2bfloat162_rn(sc[tb2][0], sc[tb2][1]); f = __bfloat1622float2(h);
                l = __floats2bfloat162_rn(sc[tb2][0] - f.x, sc[tb2][1] - f.y);
                pah[2] = *(uint32_t*)&h; pal[2] = *(uint32_t*)&l;
                h = __floats2bfloat162_rn(sc[tb2][2], sc[tb2][3]); f = __bfloat1622float2(h);
                l = __floats2bfloat162_rn(sc[tb2][2] - f.x, sc[tb2][3] - f.y);
                pah[3] = *(uint32_t*)&h; pal[3] = *(uint32_t*)&l;
            }
            #pragma unroll
            for (int np = 0; np < 4; np++) {
                uint32_t vbh[4], vbl[4];
                uint32_t rowB = (np * 16 + lr + ls8) * AT_STRIDE + kk2 * 32 + lc16;
                LDSM4(vbh, stb + AT_VH + rowB);
                LDSM4(vbl, stb + AT_VL + rowB);
                #pragma unroll
                for (int s = 0; s < 2; s++) {
                    const int nt = np * 2 + s;
                    MMA16816(O[nt], pah, vbh[s], vbh[s + 2]);
                    MMA16816(O[nt], pah, vbl[s], vbl[s + 2]);
                    MMA16816(O[nt], pal, vbh[s], vbh[s + 2]);
                }
            }
        }
        __syncthreads();
    }

    // ---- epilogue ----
    float L0 = lr0s + __shfl_xor_sync(0xffffffffu, lr0s, 1);
    L0 += __shfl_xor_sync(0xffffffffu, L0, 2);
    float L1 = lr1s + __shfl_xor_sync(0xffffffffu, lr1s, 1);
    L1 += __shfl_xor_sync(0xffffffffu, L1, 2);
    float inv0 = (L0 > 0.f) ? 1.f / L0 : 0.f;
    float inv1 = (L1 > 0.f) ? 1.f / L1 : 0.f;

    #pragma unroll
    for (int nt = 0; nt < 8; nt++) {
        *(float2*)&g_ao[ho + (size_t)qg0 * D_HEAD + nt * 8 + c2] =
            make_float2(O[nt][0] * inv0, O[nt][1] * inv0);
        *(float2*)&g_ao[ho + (size_t)(qg0 + 8) * D_HEAD + nt * 8 + c2] =
            make_float2(O[nt][2] * inv1, O[nt][3] * inv1);
    }
}

// ---------------------------------------------------------------------------
extern "C" void kernel_launch(void* const* d_in, const int* in_sizes, int n_in,
                              void* d_out, int out_size)
{
    const float* q    = (const float*)d_in[0];
    const float* k    = (const float*)d_in[1];
    const float* v    = (const float*)d_in[2];
    const int*   mask = (const int*)d_in[3];
    const float* w_q  = (const float*)d_in[4];
    const float* w_k  = (const float*)d_in[5];
    const float* w_v  = (const float*)d_in[6];
    const float* w_o  = (const float*)d_in[7];
    float* out = (float*)d_out;

    float *pq, *pk, *pv, *pa;
    __nv_bfloat16 *pah, *pal, *pwh, *pwl, *pqh, *pql, *pkh, *pkl;
    cudaGetSymbolAddress((void**)&pq,  g_q);
    cudaGetSymbolAddress((void**)&pk,  g_k);
    cudaGetSymbolAddress((void**)&pv,  g_v);
    cudaGetSymbolAddress((void**)&pa,  g_ao);
    cudaGetSymbolAddress((void**)&pah, g_ah);
    cudaGetSymbolAddress((void**)&pal, g_al);
    cudaGetSymbolAddress((void**)&pwh, g_wh);
    cudaGetSymbolAddress((void**)&pwl, g_wl);
    cudaGetSymbolAddress((void**)&pqh, g_qh);
    cudaGetSymbolAddress((void**)&pql, g_ql);
    cudaGetSymbolAddress((void**)&pkh, g_kh);
    cudaGetSymbolAddress((void**)&pkl, g_kl);

    cudaFuncSetAttribute(gemm_tc, cudaFuncAttributeMaxDynamicSharedMemorySize, GSMEM);
    cudaFuncSetAttribute(attn_tc, cudaFuncAttributeMaxDynamicSharedMemorySize, AT_SMEM);

    const int nA4 = M_ROWS * D_MODEL / 4;
    const int nW4 = D_MODEL * D_MODEL / 4;
    dim3 gg(D_MODEL / 128, M_ROWS / 128);

    maskpack<<<B_ * S_ * 64 * 32 / 256, 256>>>(mask);

    split_f32<<<nA4 / 256, 256>>>(q,   pah, pal, nA4, 1.f);
    split_f32<<<nW4 / 256, 256>>>(w_q, pwh, pwl, nW4, 1.f);
    gemm_tc<<<gg, 256, GSMEM>>>(pah, pal, pwh, pwl, pq);

    split_f32<<<nA4 / 256, 256>>>(k,   pah, pal, nA4, 1.f);
    split_f32<<<nW4 / 256, 256>>>(w_k, pwh, pwl, nW4, 1.f);
    gemm_tc<<<gg, 256, GSMEM>>>(pah, pal, pwh, pwl, pk);

    split_f32<<<nA4 / 256, 256>>>(v,   pah, pal, nA4, 1.f);
    split_f32<<<nW4 / 256, 256>>>(w_v, pwh, pwl, nW4, 1.f);
    gemm_tc<<<gg, 256, GSMEM>>>(pah, pal, pwh, pwl, pv);

    // attention prep: scaled-Q split, K split, V transpose-split
    split_f32<<<nA4 / 256, 256>>>(pq, pqh, pql, nA4, 0.125f);
    split_f32<<<nA4 / 256, 256>>>(pk, pkh, pkl, nA4, 1.f);
    vtrans_split<<<dim3(S_ / 32, D_HEAD / 32, B_ * NHEAD), dim3(32, 8)>>>();

    attn_tc<<<dim3(S_ / 128, B_ * NHEAD), 256, AT_SMEM>>>();

    split_f32<<<nA4 / 256, 256>>>(pa,  pah, pal, nA4, 1.f);
    split_f32<<<nW4 / 256, 256>>>(w_o, pwh, pwl, nW4, 1.f);
    gemm_tc<<<gg, 256, GSMEM>>>(pah, pal, pwh, pwl, out);
}

// round 6
// speedup vs baseline: 2.6072x; 1.0003x over previous
#include <cuda_runtime.h>
#include <cuda_bf16.h>
#include <math.h>
#include <stdint.h>

#define D_MODEL 1024
#define NHEAD   16
#define D_HEAD  64
#define B_      2
#define S_      2048
#define M_ROWS  (B_*S_)     // 4096

// ---------------- scratch (allocation-free) ----------------
__device__ float g_q [M_ROWS * D_MODEL];
__device__ float g_k [M_ROWS * D_MODEL];
__device__ float g_v [M_ROWS * D_MODEL];
__device__ float g_ao[M_ROWS * D_MODEL];
__device__ __nv_bfloat16 g_ah[M_ROWS * D_MODEL];
__device__ __nv_bfloat16 g_al[M_ROWS * D_MODEL];
__device__ __nv_bfloat16 g_wh[D_MODEL * D_MODEL];
__device__ __nv_bfloat16 g_wl[D_MODEL * D_MODEL];
__device__ __nv_bfloat16 g_qh[M_ROWS * D_MODEL];
__device__ __nv_bfloat16 g_ql[M_ROWS * D_MODEL];
__device__ __nv_bfloat16 g_kh[M_ROWS * D_MODEL];
__device__ __nv_bfloat16 g_kl[M_ROWS * D_MODEL];
__device__ __nv_bfloat16 g_vth[M_ROWS * D_MODEL];
__device__ __nv_bfloat16 g_vtl[M_ROWS * D_MODEL];
__device__ uint32_t      g_mbits[B_ * S_ * (S_/32)];

// ---------------- helpers ----------------
__device__ __forceinline__ uint32_t smem_u32(const void* p) {
    uint32_t a;
    asm("{ .reg .u64 t; cvta.to.shared.u64 t, %1; cvt.u32.u64 %0, t; }" : "=r"(a) : "l"(p));
    return a;
}
#define CP16(dst, src) \
    asm volatile("cp.async.cg.shared.global [%0], [%1], 16;" :: "r"(dst), "l"(src))
#define CP_COMMIT() asm volatile("cp.async.commit_group;" ::: "memory")
#define LDSM4(d, a) \
    asm volatile("ldmatrix.sync.aligned.m8n8.x4.shared.b16 {%0,%1,%2,%3}, [%4];" \
        : "=r"((d)[0]), "=r"((d)[1]), "=r"((d)[2]), "=r"((d)[3]) : "r"(a))
#define MMA16816(c, a, b0, b1) \
    asm volatile("mma.sync.aligned.m16n8k16.row.col.f32.bf16.bf16.f32 " \
        "{%0,%1,%2,%3},{%4,%5,%6,%7},{%8,%9},{%0,%1,%2,%3};" \
        : "+f"((c)[0]), "+f"((c)[1]), "+f"((c)[2]), "+f"((c)[3]) \
        : "r"((a)[0]), "r"((a)[1]), "r"((a)[2]), "r"((a)[3]), "r"(b0), "r"(b1))

// ---------------- fp32 -> (hi,lo) bf16 split, optional scale ----------------
__global__ __launch_bounds__(256) void split_f32(
    const float* __restrict__ x, __nv_bfloat16* __restrict__ hi,
    __nv_bfloat16* __restrict__ lo, int n4, float scale)
{
    int i = blockIdx.x * blockDim.x + threadIdx.x;
    if (i >= n4) return;
    float4 v = ((const float4*)x)[i];
    v.x *= scale; v.y *= scale; v.z *= scale; v.w *= scale;
    __nv_bfloat162 h01 = __floats2bfloat162_rn(v.x, v.y);
    __nv_bfloat162 h23 = __floats2bfloat162_rn(v.z, v.w);
    float2 f01 = __bfloat1622float2(h01);
    float2 f23 = __bfloat1622float2(h23);
    __nv_bfloat162 l01 = __floats2bfloat162_rn(v.x - f01.x, v.y - f01.y);
    __nv_bfloat162 l23 = __floats2bfloat162_rn(v.z - f23.x, v.w - f23.y);
    uint2 hp, lp;
    hp.x = *reinterpret_cast<uint32_t*>(&h01); hp.y = *reinterpret_cast<uint32_t*>(&h23);
    lp.x = *reinterpret_cast<uint32_t*>(&l01); lp.y = *reinterpret_cast<uint32_t*>(&l23);
    ((uint2*)hi)[i] = hp;
    ((uint2*)lo)[i] = lp;
}

// ---------------- V transpose + split ----------------
__global__ __launch_bounds__(256) void vtrans_split(void)
{
    __shared__ float t[32][33];
    const int bh = blockIdx.z, kt = blockIdx.x, dt = blockIdx.y;
    const int tx = threadIdx.x, ty = threadIdx.y;
    const size_t ho = (size_t)bh * S_ * D_HEAD;
    #pragma unroll
    for (int i = 0; i < 4; i++) {
        int key = kt * 32 + ty + i * 8;
        t[ty + i * 8][tx] = g_v[ho + (size_t)key * D_HEAD + dt * 32 + tx];
    }
    __syncthreads();
    #pragma unroll
    for (int i = 0; i < 4; i++) {
        int d   = dt * 32 + ty + i * 8;
        int key = kt * 32 + tx;
        float f = t[tx][ty + i * 8];
        __nv_bfloat16 h = __float2bfloat16_rn(f);
        g_vth[ho + (size_t)d * S_ + key] = h;
        g_vtl[ho + (size_t)d * S_ + key] = __float2bfloat16_rn(f - __bfloat162float(h));
    }
}

// ---------------- mask int32 -> bitmask ----------------
__global__ __launch_bounds__(256) void maskpack(const int* __restrict__ mask)
{
    int g = blockIdx.x * blockDim.x + threadIdx.x;
    int wid = g >> 5, lane = g & 31;
    int m = mask[((size_t)(wid >> 6) << 11) + ((wid & 63) << 5) + lane];
    uint32_t word = __ballot_sync(0xffffffffu, m != 0);
    if (lane == 0) g_mbits[wid] = word;
}

// ---------------- split-bf16 GEMM: 512 threads, warp grid 4x4 ----------------
#define GS_STRIDE 80
#define GS_TILE   (128 * GS_STRIDE)
#define GS_STAGE  (4 * GS_TILE)
#define GSMEM     (2 * GS_STAGE)
#define NKB       (D_MODEL / 32)

__global__ __launch_bounds__(512) void gemm_tc(
    const __nv_bfloat16* __restrict__ Ah, const __nv_bfloat16* __restrict__ Al,
    const __nv_bfloat16* __restrict__ Wh, const __nv_bfloat16* __restrict__ Wl,
    float* __restrict__ C)
{
    extern __shared__ char sm[];
    const uint32_t sbase = smem_u32(sm);
    const int tid  = threadIdx.x;
    const int wid  = tid >> 5, lane = tid & 31;
    const int wm   = wid & 3,  wn   = wid >> 2;       // 4x4 warp grid
    const int m0   = blockIdx.y * 128, n0 = blockIdx.x * 128;

    const __nv_bfloat16* srcs[4] = {Ah, Al, Wh, Wl};
    const int rb[4] = {m0, m0, n0, n0};

    auto load_stage = [&](int kb, int s) {
        const int k0 = kb * 32;
        const uint32_t stb = sbase + s * GS_STAGE;
        #pragma unroll
        for (int j = 0; j < 4; j++) {
            int c    = j * 512 + tid;            // 0..2047
            int tile = c >> 9;
            int r    = (c >> 2) & 127;
            int cc   = c & 3;
            uint32_t dst = stb + tile * GS_TILE + r * GS_STRIDE + cc * 16;
            const __nv_bfloat16* src = srcs[tile] + ((size_t)(rb[tile] + r) << 10) + k0 + cc * 8;
            CP16(dst, src);
        }
        CP_COMMIT();
    };

    float acc[2][4][4];
    #pragma unroll
    for (int mt = 0; mt < 2; mt++)
        #pragma unroll
        for (int nt = 0; nt < 4; nt++)
            #pragma unroll
            for (int e = 0; e < 4; e++) acc[mt][nt][e] = 0.f;

    const int lr   = lane & 7;
    const int ls8  = ((lane >> 3) & 1) << 3;
    const int lc16 = ((lane >> 4) & 1) << 4;

    load_stage(0, 0);

    for (int kb = 0; kb < NKB; kb++) {
        if (kb + 1 < NKB) {
            load_stage(kb + 1, (kb + 1) & 1);
            asm volatile("cp.async.wait_group 1;" ::: "memory");
        } else {
            asm volatile("cp.async.wait_group 0;" ::: "memory");
        }
        __syncthreads();

        const uint32_t stb = sbase + (kb & 1) * GS_STAGE;
        #pragma unroll
        for (int k16 = 0; k16 < 2; k16++) {
            const uint32_t colOff = k16 * 32 + lc16;
            uint32_t ah[2][4], al[2][4], bh[2][4], bl[2][4];
            #pragma unroll
            for (int mt = 0; mt < 2; mt++) {
                uint32_t rowA = wm * 32 + mt * 16 + lr + ls8;
                LDSM4(ah[mt], stb + 0 * GS_TILE + rowA * GS_STRIDE + colOff);
                LDSM4(al[mt], stb + 1 * GS_TILE + rowA * GS_STRIDE + colOff);
            }
            #pragma unroll
            for (int np = 0; np < 2; np++) {
                uint32_t rowB = wn * 32 + np * 16 + lr + ls8;
                LDSM4(bh[np], stb + 2 * GS_TILE + rowB * GS_STRIDE + colOff);
                LDSM4(bl[np], stb + 3 * GS_TILE + rowB * GS_STRIDE + colOff);
            }
            #pragma unroll
            for (int mt = 0; mt < 2; mt++)
                #pragma unroll
                for (int nt = 0; nt < 4; nt++) {
                    const int np = nt >> 1, s = nt & 1;
                    MMA16816(acc[mt][nt], ah[mt], bh[np][s], bh[np][s + 2]);
                    MMA16816(acc[mt][nt], ah[mt], bl[np][s], bl[np][s + 2]);
                    MMA16816(acc[mt][nt], al[mt], bh[np][s], bh[np][s + 2]);
                }
        }
        __syncthreads();
    }

    const int erow = lane >> 2, ecol = (lane & 3) << 1;
    #pragma unroll
    for (int mt = 0; mt < 2; mt++)
        #pragma unroll
        for (int nt = 0; nt < 4; nt++) {
            int gr = m0 + wm * 32 + mt * 16 + erow;
            int gc = n0 + wn * 32 + nt * 8 + ecol;
            *(float2*)&C[(size_t)gr * D_MODEL + gc] =
                make_float2(acc[mt][nt][0], acc[mt][nt][1]);
            *(float2*)&C[(size_t)(gr + 8) * D_MODEL + gc] =
                make_float2(acc[mt][nt][2], acc[mt][nt][3]);
        }
}

// ---------------- tensor-core flash attention: 512 threads, 256 q-rows ----------------
#define AT_STRIDE 144
#define AT_QH 0
#define AT_QL (256 * AT_STRIDE)          // 36864
#define AT_S0 (2 * 256 * AT_STRIDE)      // 73728
#define AT_KH 0
#define AT_KL 9216
#define AT_VH 18432
#define AT_VL 27648
#define AT_STAGE 36864
#define AT_SMEM (AT_S0 + 2 * AT_STAGE)   // 147456
#define AT_NT (S_ / 64)                  // 32 k-tiles

__global__ __launch_bounds__(512) void attn_tc(void)
{
    extern __shared__ char sm[];
    const uint32_t sbase = smem_u32(sm);
    const int tid = threadIdx.x, wid = tid >> 5, lane = tid & 31;
    const int bh  = blockIdx.y, b = bh >> 4;
    const int qBase = blockIdx.x * 256;
    const size_t ho = (size_t)bh * S_ * D_HEAD;

    const int lr   = lane & 7;
    const int ls8  = ((lane >> 3) & 1) << 3;
    const int lc16 = ((lane >> 4) & 1) << 4;
    const int r0   = lane >> 2, c2 = (lane & 3) << 1;

    // ---- load Q (256 rows, hi+lo) ----
    #pragma unroll
    for (int j = 0; j < 8; j++) {
        int c = j * 512 + tid;               // 0..4095
        int t = c >> 11, r = (c >> 3) & 255, cc = c & 7;
        uint32_t dst = sbase + (t ? AT_QL : AT_QH) + r * AT_STRIDE + cc * 16;
        const __nv_bfloat16* src = (t ? g_ql : g_qh) + ho + (size_t)(qBase + r) * D_HEAD + cc * 8;
        CP16(dst, src);
    }
    CP_COMMIT();

    auto load_stage = [&](int kt, int s) {
        const int k0 = kt * 64;
        const uint32_t stb = sbase + AT_S0 + s * AT_STAGE;
        #pragma unroll
        for (int j = 0; j < 4; j++) {
            int c = j * 512 + tid;           // 0..2047
            int t = c >> 9, r = (c >> 3) & 63, cc = c & 7;
            uint32_t dst = stb + t * 9216 + r * AT_STRIDE + cc * 16;
            const __nv_bfloat16* src;
            if      (t == 0) src = g_kh  + ho + (size_t)(k0 + r) * D_HEAD + cc * 8;
            else if (t == 1) src = g_kl  + ho + (size_t)(k0 + r) * D_HEAD + cc * 8;
            else if (t == 2) src = g_vth + ho + (size_t)r * S_ + k0 + cc * 8;
            else             src = g_vtl + ho + (size_t)r * S_ + k0 + cc * 8;
            CP16(dst, src);
        }
        CP_COMMIT();
    };

    load_stage(0, 0);
    asm volatile("cp.async.wait_group 0;" ::: "memory");
    __syncthreads();

    float O[8][4];
    #pragma unroll
    for (int nt = 0; nt < 8; nt++)
        #pragma unroll
        for (int e = 0; e < 4; e++) O[nt][e] = 0.f;
    float mr0 = -INFINITY, mr1 = -INFINITY, lr0s = 0.f, lr1s = 0.f;

    const int qg0 = qBase + wid * 16 + r0;
    const size_t mrow0 = ((size_t)b * S_ + qg0) * (S_ / 32);
    const size_t mrow1 = mrow0 + 8 * (S_ / 32);
    const uint32_t rowA = (wid * 16 + lr + ls8) * AT_STRIDE;

    for (int kt = 0; kt < AT_NT; kt++) {
        if (kt + 1 < AT_NT) {
            load_stage(kt + 1, (kt + 1) & 1);
            asm volatile("cp.async.wait_group 1;" ::: "memory");
        } else {
            asm volatile("cp.async.wait_group 0;" ::: "memory");
        }
        __syncthreads();

        const uint32_t stb = sbase + AT_S0 + (kt & 1) * AT_STAGE;

        // ---- scores: 3-pass split MMA (Q frags re-loaded from smem) ----
        float sc[8][4];
        #pragma unroll
        for (int nt = 0; nt < 8; nt++)
            #pragma unroll
            for (int e = 0; e < 4; e++) sc[nt][e] = 0.f;

        #pragma unroll
        for (int kk = 0; kk < 4; kk++) {
            uint32_t qhf[4], qlf[4];
            LDSM4(qhf, sbase + AT_QH + rowA + kk * 32 + lc16);
            LDSM4(qlf, sbase + AT_QL + rowA + kk * 32 + lc16);
            #pragma unroll
            for (int np = 0; np < 4; np++) {
                uint32_t kbh[4], kbl[4];
                uint32_t rowB = (np * 16 + lr + ls8) * AT_STRIDE + kk * 32 + lc16;
                LDSM4(kbh, stb + AT_KH + rowB);
                LDSM4(kbl, stb + AT_KL + rowB);
                #pragma unroll
                for (int s = 0; s < 2; s++) {
                    const int nt = np * 2 + s;
                    MMA16816(sc[nt], qhf, kbh[s], kbh[s + 2]);
                    MMA16816(sc[nt], qhf, kbl[s], kbl[s + 2]);
                    MMA16816(sc[nt], qlf, kbh[s], kbh[s + 2]);
                }
            }
        }

        // ---- mask ----
        uint32_t mw00 = g_mbits[mrow0 + kt * 2], mw01 = g_mbits[mrow0 + kt * 2 + 1];
        uint32_t mw10 = g_mbits[mrow1 + kt * 2], mw11 = g_mbits[mrow1 + kt * 2 + 1];
        #pragma unroll
        for (int nt = 0; nt < 8; nt++) {
            #pragma unroll
            for (int e = 0; e < 4; e++) {
                int key = nt * 8 + c2 + (e & 1);
                uint32_t word = (e < 2) ? ((key < 32) ? mw00 : mw01)
                                        : ((key < 32) ? mw10 : mw11);
                if ((word >> (key & 31)) & 1u) sc[nt][e] = -INFINITY;
            }
        }

        // ---- online softmax ----
        float tm0 = -INFINITY, tm1 = -INFINITY;
        #pragma unroll
        for (int nt = 0; nt < 8; nt++) {
            tm0 = fmaxf(tm0, fmaxf(sc[nt][0], sc[nt][1]));
            tm1 = fmaxf(tm1, fmaxf(sc[nt][2], sc[nt][3]));
        }
        tm0 = fmaxf(tm0, __shfl_xor_sync(0xffffffffu, tm0, 1));
        tm0 = fmaxf(tm0, __shfl_xor_sync(0xffffffffu, tm0, 2));
        tm1 = fmaxf(tm1, __shfl_xor_sync(0xffffffffu, tm1, 1));
        tm1 = fmaxf(tm1, __shfl_xor_sync(0xffffffffu, tm1, 2));

        float nm0 = fmaxf(mr0, tm0), nm1 = fmaxf(mr1, tm1);
        float corr0 = (mr0 == -INFINITY) ? 1.f : __expf(mr0 - nm0);
        float corr1 = (mr1 == -INFINITY) ? 1.f : __expf(mr1 - nm1);
        float b0 = (nm0 == -INFINITY) ? 0.f : nm0;
        float b1 = (nm1 == -INFINITY) ? 0.f : nm1;

        float ps0 = 0.f, ps1 = 0.f;
        #pragma unroll
        for (int nt = 0; nt < 8; nt++) {
            float p0 = __expf(sc[nt][0] - b0), p1 = __expf(sc[nt][1] - b0);
            float p2 = __expf(sc[nt][2] - b1), p3 = __expf(sc[nt][3] - b1);
            sc[nt][0] = p0; sc[nt][1] = p1; sc[nt][2] = p2; sc[nt][3] = p3;
            ps0 += p0 + p1; ps1 += p2 + p3;
        }
        lr0s = lr0s * corr0 + ps0;
        lr1s = lr1s * corr1 + ps1;
        mr0 = nm0; mr1 = nm1;
        #pragma unroll
        for (int nt = 0; nt < 8; nt++) {
            O[nt][0] *= corr0; O[nt][1] *= corr0;
            O[nt][2] *= corr1; O[nt][3] *= corr1;
        }

        // ---- PV: 3-pass split MMA, P repacked in-register ----
        #pragma unroll
        for (int kk2 = 0; kk2 < 4; kk2++) {
            uint32_t pah[4], pal[4];
            {
                const int ta = 2 * kk2, tb2 = 2 * kk2 + 1;
                __nv_bfloat162 h, l; float2 f;
                h = __floats2bfloat162_rn(sc[ta][0], sc[ta][1]);  f = __bfloat1622float2(h);
                l = __floats2bfloat162_rn(sc[ta][0] - f.x, sc[ta][1] - f.y);
                pah[0] = *(uint32_t*)&h; pal[0] = *(uint32_t*)&l;
                h = __floats2bfloat162_rn(sc[ta][2], sc[ta][3]);  f = __bfloat1622float2(h);
                l = __floats2bfloat162_rn(sc[ta][2] - f.x, sc[ta][3] - f.y);
                pah[1] = *(uint32_t*)&h; pal[1] = *(uint32_t*)&l;
                h = __floats2bfloat162_rn(sc[tb2][0], sc[tb2][1]); f = __bfloat1622float2(h);
                l = __floats2bfloat162_rn(sc[tb2][0] - f.x, sc[tb2][1] - f.y);
                pah[2] = *(uint32_t*)&h; pal[2] = *(uint32_t*)&l;
                h = __floats2bfloat162_rn(sc[tb2][2], sc[tb2][3]); f = __bfloat1622float2(h);
                l = __floats2bfloat162_rn(sc[tb2][2] - f.x, sc[tb2][3] - f.y);
                pah[3] = *(uint32_t*)&h; pal[3] = *(uint32_t*)&l;
            }
            #pragma unroll
            for (int np = 0; np < 4; np++) {
                uint32_t vbh[4], vbl[4];
                uint32_t rowB = (np * 16 + lr + ls8) * AT_STRIDE + kk2 * 32 + lc16;
                LDSM4(vbh, stb + AT_VH + rowB);
                LDSM4(vbl, stb + AT_VL + rowB);
                #pragma unroll
                for (int s = 0; s < 2; s++) {
                    const int nt = np * 2 + s;
                    MMA16816(O[nt], pah, vbh[s], vbh[s + 2]);
                    MMA16816(O[nt], pah, vbl[s], vbl[s + 2]);
                    MMA16816(O[nt], pal, vbh[s], vbh[s + 2]);
                }
            }
        }
        __syncthreads();
    }

    // ---- epilogue ----
    float L0 = lr0s + __shfl_xor_sync(0xffffffffu, lr0s, 1);
    L0 += __shfl_xor_sync(0xffffffffu, L0, 2);
    float L1 = lr1s + __shfl_xor_sync(0xffffffffu, lr1s, 1);
    L1 += __shfl_xor_sync(0xffffffffu, L1, 2);
    float inv0 = (L0 > 0.f) ? 1.f / L0 : 0.f;
    float inv1 = (L1 > 0.f) ? 1.f / L1 : 0.f;

    #pragma unroll
    for (int nt = 0; nt < 8; nt++) {
        *(float2*)&g_ao[ho + (size_t)qg0 * D_HEAD + nt * 8 + c2] =
            make_float2(O[nt][0] * inv0, O[nt][1] * inv0);
        *(float2*)&g_ao[ho + (size_t)(qg0 + 8) * D_HEAD + nt * 8 + c2] =
            make_float2(O[nt][2] * inv1, O[nt][3] * inv1);
    }
}

// ---------------------------------------------------------------------------
extern "C" void kernel_launch(void* const* d_in, const int* in_sizes, int n_in,
                              void* d_out, int out_size)
{
    const float* q    = (const float*)d_in[0];
    const float* k    = (const float*)d_in[1];
    const float* v    = (const float*)d_in[2];
    const int*   mask = (const int*)d_in[3];
    const float* w_q  = (const float*)d_in[4];
    const float* w_k  = (const float*)d_in[5];
    const float* w_v  = (const float*)d_in[6];
    const float* w_o  = (const float*)d_in[7];
    float* out = (float*)d_out;

    float *pq, *pk, *pv, *pa;
    __nv_bfloat16 *pah, *pal, *pwh, *pwl, *pqh, *pql, *pkh, *pkl;
    cudaGetSymbolAddress((void**)&pq,  g_q);
    cudaGetSymbolAddress((void**)&pk,  g_k);
    cudaGetSymbolAddress((void**)&pv,  g_v);
    cudaGetSymbolAddress((void**)&pa,  g_ao);
    cudaGetSymbolAddress((void**)&pah, g_ah);
    cudaGetSymbolAddress((void**)&pal, g_al);
    cudaGetSymbolAddress((void**)&pwh, g_wh);
    cudaGetSymbolAddress((void**)&pwl, g_wl);
    cudaGetSymbolAddress((void**)&pqh, g_qh);
    cudaGetSymbolAddress((void**)&pql, g_ql);
    cudaGetSymbolAddress((void**)&pkh, g_kh);
    cudaGetSymbolAddress((void**)&pkl, g_kl);

    cudaFuncSetAttribute(gemm_tc, cudaFuncAttributeMaxDynamicSharedMemorySize, GSMEM);
    cudaFuncSetAttribute(attn_tc, cudaFuncAttributeMaxDynamicSharedMemorySize, AT_SMEM);

    const int nA4 = M_ROWS * D_MODEL / 4;
    const int nW4 = D_MODEL * D_MODEL / 4;
    dim3 gg(D_MODEL / 128, M_ROWS / 128);

    maskpack<<<B_ * S_ * 64 * 32 / 256, 256>>>(mask);

    split_f32<<<nA4 / 256, 256>>>(q,   pah, pal, nA4, 1.f);
    split_f32<<<nW4 / 256, 256>>>(w_q, pwh, pwl, nW4, 1.f);
    gemm_tc<<<gg, 512, GSMEM>>>(pah, pal, pwh, pwl, pq);

    split_f32<<<nA4 / 256, 256>>>(k,   pah, pal, nA4, 1.f);
    split_f32<<<nW4 / 256, 256>>>(w_k, pwh, pwl, nW4, 1.f);
    gemm_tc<<<gg, 512, GSMEM>>>(pah, pal, pwh, pwl, pk);

    split_f32<<<nA4 / 256, 256>>>(v,   pah, pal, nA4, 1.f);
    split_f32<<<nW4 / 256, 256>>>(w_v, pwh, pwl, nW4, 1.f);
    gemm_tc<<<gg, 512, GSMEM>>>(pah, pal, pwh, pwl, pv);

    split_f32<<<nA4 / 256, 256>>>(pq, pqh, pql, nA4, 0.125f);
    split_f32<<<nA4 / 256, 256>>>(pk, pkh, pkl, nA4, 1.f);
    vtrans_split<<<dim3(S_ / 32, D_HEAD / 32, B_ * NHEAD), dim3(32, 8)>>>();

    attn_tc<<<dim3(S_ / 256, B_ * NHEAD), 512, AT_SMEM>>>();

    split_f32<<<nA4 / 256, 256>>>(pa,  pah, pal, nA4, 1.f);
    split_f32<<<nW4 / 256, 256>>>(w_o, pwh, pwl, nW4, 1.f);
    gemm_tc<<<gg, 512, GSMEM>>>(pah, pal, pwh, pwl, out);
}